// round 8
// baseline (speedup 1.0000x reference)
#include <cuda_runtime.h>
#include <math.h>

#define BATCH  128
#define KK     512
#define NSL    16     // i-slices of 32 rows (both big kernels)
#define SLR    32     // rows per slice
#define TPB    128    // thread owns 4 columns (float4)

#define LOGK 6.2383246250395077632f   // log(512)

// Scratch (__device__ globals; allocation-free rule). Fully overwritten per launch.
__device__ float g_Ep[2 * NSL * BATCH * KK];   // partial col-sums Q0/Q1 (8 MB)
__device__ float g_mmp[NSL * BATCH * KK];      // partial mm sums (4 MB)
__device__ float g_ew[BATCH * KK];             // exp(P0)*K/E1
__device__ float g_E0inv[BATCH * KK];          // 1/E0
__device__ float g_sb[BATCH];                  // per-batch logK - log(sum_j t)
__device__ unsigned int g_tickA[BATCH];        // per-batch tickets, kernel 1
__device__ unsigned int g_tickB[BATCH];        // per-batch tickets, kernel 2
__device__ unsigned int g_tickF;               // global final ticket

__device__ __forceinline__ float4 ldcs4(const float4* p) {
    return __ldcs(p);
}

// ---------------------------------------------------------------------------
// Kernel 1: partial column sums of exp() for Q0 and Q1 (float4, streaming).
// grid = (2*NSL, BATCH) = 4096 blocks. Last-finishing block of each batch
// computes ew[b,:] = exp(P0)*K/E1 and E0inv[b,:] = 1/E0 (L2-hot partials).
// ---------------------------------------------------------------------------
__global__ void __launch_bounds__(TPB) k_colsum(const float* __restrict__ Q0,
                                                const float* __restrict__ Q1,
                                                const float* __restrict__ P0)
{
    const int which = blockIdx.x >> 4;
    const int slice = blockIdx.x & 15;
    const int b     = blockIdx.y;
    const int t     = threadIdx.x;

    const float* __restrict__ src = which ? Q1 : Q0;
    const float4* p = (const float4*)(src + (size_t)b * KK * KK
                                          + (size_t)(slice * SLR) * KK) + t;
    const int rs = KK / 4;

    float sx = 0.f, sy = 0.f, sz = 0.f, sw = 0.f;
#pragma unroll
    for (int i = 0; i < SLR; i += 8) {
        float4 a0 = ldcs4(p + (i + 0) * rs);
        float4 a1 = ldcs4(p + (i + 1) * rs);
        float4 a2 = ldcs4(p + (i + 2) * rs);
        float4 a3 = ldcs4(p + (i + 3) * rs);
        float4 a4 = ldcs4(p + (i + 4) * rs);
        float4 a5 = ldcs4(p + (i + 5) * rs);
        float4 a6 = ldcs4(p + (i + 6) * rs);
        float4 a7 = ldcs4(p + (i + 7) * rs);
        sx += __expf(a0.x) + __expf(a1.x) + __expf(a2.x) + __expf(a3.x)
            + __expf(a4.x) + __expf(a5.x) + __expf(a6.x) + __expf(a7.x);
        sy += __expf(a0.y) + __expf(a1.y) + __expf(a2.y) + __expf(a3.y)
            + __expf(a4.y) + __expf(a5.y) + __expf(a6.y) + __expf(a7.y);
        sz += __expf(a0.z) + __expf(a1.z) + __expf(a2.z) + __expf(a3.z)
            + __expf(a4.z) + __expf(a5.z) + __expf(a6.z) + __expf(a7.z);
        sw += __expf(a0.w) + __expf(a1.w) + __expf(a2.w) + __expf(a3.w)
            + __expf(a4.w) + __expf(a5.w) + __expf(a6.w) + __expf(a7.w);
    }
    ((float4*)(g_Ep + ((size_t)blockIdx.x * BATCH + b) * KK))[t] =
        make_float4(sx, sy, sz, sw);

    // --- per-batch ticket epilogue: last of 32 blocks builds ew / E0inv ---
    __threadfence();
    __syncthreads();
    __shared__ bool amLast;
    if (t == 0)
        amLast = (atomicAdd(&g_tickA[b], 1u) == 2 * NSL - 1);
    __syncthreads();

    if (amLast) {
#pragma unroll
        for (int c = 0; c < 4; c++) {
            const int i = c * TPB + t;
            float e0 = 0.f, e1 = 0.f;
#pragma unroll
            for (int s = 0; s < NSL; s++) {
                e0 += g_Ep[((size_t)s         * BATCH + b) * KK + i];
                e1 += g_Ep[((size_t)(NSL + s) * BATCH + b) * KK + i];
            }
            g_E0inv[b * KK + i] = 1.0f / e0;
            g_ew[b * KK + i]    = __expf(P0[b * KK + i]) * (float)KK / e1;
        }
        if (t == 0) g_tickA[b] = 0;   // reset for graph replay
    }
}

// ---------------------------------------------------------------------------
// Kernel 2: partial mm[b,j] = sum_{i in slice} ew[b,i]*exp(P1[b,i,j]).
// grid = (NSL, BATCH) = 2048 blocks. Last-finishing block of each batch
// computes g_sb[b]; global ticket -> deterministic batch tree-sum -> out.
// ---------------------------------------------------------------------------
__global__ void __launch_bounds__(TPB) k_mid(const float* __restrict__ P1,
                                             const float* __restrict__ P2,
                                             float* __restrict__ out)
{
    const int slice = blockIdx.x;
    const int b     = blockIdx.y;
    const int t     = threadIdx.x;

    __shared__ float ew[SLR];
    if (t < SLR) ew[t] = g_ew[b * KK + slice * SLR + t];
    __syncthreads();

    const float4* p = (const float4*)(P1 + (size_t)b * KK * KK
                                         + (size_t)(slice * SLR) * KK) + t;
    const int rs = KK / 4;

    float sx = 0.f, sy = 0.f, sz = 0.f, sw = 0.f;
#pragma unroll
    for (int i = 0; i < SLR; i += 8) {
        float4 a0 = ldcs4(p + (i + 0) * rs);
        float4 a1 = ldcs4(p + (i + 1) * rs);
        float4 a2 = ldcs4(p + (i + 2) * rs);
        float4 a3 = ldcs4(p + (i + 3) * rs);
        float4 a4 = ldcs4(p + (i + 4) * rs);
        float4 a5 = ldcs4(p + (i + 5) * rs);
        float4 a6 = ldcs4(p + (i + 6) * rs);
        float4 a7 = ldcs4(p + (i + 7) * rs);
        float w0 = ew[i + 0], w1 = ew[i + 1], w2 = ew[i + 2], w3 = ew[i + 3];
        float w4 = ew[i + 4], w5 = ew[i + 5], w6 = ew[i + 6], w7 = ew[i + 7];
        sx += w0 * __expf(a0.x) + w1 * __expf(a1.x)
            + w2 * __expf(a2.x) + w3 * __expf(a3.x)
            + w4 * __expf(a4.x) + w5 * __expf(a5.x)
            + w6 * __expf(a6.x) + w7 * __expf(a7.x);
        sy += w0 * __expf(a0.y) + w1 * __expf(a1.y)
            + w2 * __expf(a2.y) + w3 * __expf(a3.y)
            + w4 * __expf(a4.y) + w5 * __expf(a5.y)
            + w6 * __expf(a6.y) + w7 * __expf(a7.y);
        sz += w0 * __expf(a0.z) + w1 * __expf(a1.z)
            + w2 * __expf(a2.z) + w3 * __expf(a3.z)
            + w4 * __expf(a4.z) + w5 * __expf(a5.z)
            + w6 * __expf(a6.z) + w7 * __expf(a7.z);
        sw += w0 * __expf(a0.w) + w1 * __expf(a1.w)
            + w2 * __expf(a2.w) + w3 * __expf(a3.w)
            + w4 * __expf(a4.w) + w5 * __expf(a5.w)
            + w6 * __expf(a6.w) + w7 * __expf(a7.w);
    }
    ((float4*)(g_mmp + ((size_t)slice * BATCH + b) * KK))[t] =
        make_float4(sx, sy, sz, sw);

    // --- per-batch ticket epilogue: last of 16 blocks finishes batch b ---
    __threadfence();
    __syncthreads();
    __shared__ bool amLast;
    if (t == 0)
        amLast = (atomicAdd(&g_tickB[b], 1u) == NSL - 1);
    __syncthreads();

    if (amLast) {
        float acc = 0.f;
#pragma unroll
        for (int c = 0; c < 4; c++) {
            const int j = c * TPB + t;
            float m = 0.f;
#pragma unroll
            for (int s = 0; s < NSL; s++)
                m += g_mmp[((size_t)s * BATCH + b) * KK + j];
            acc += m * g_E0inv[b * KK + j] * __expf(P2[b * KK + j]);
        }
#pragma unroll
        for (int o = 16; o; o >>= 1)
            acc += __shfl_down_sync(0xFFFFFFFFu, acc, o);

        __shared__ float red[4];
        if ((t & 31) == 0) red[t >> 5] = acc;
        __syncthreads();

        __shared__ bool amFinal;
        if (t == 0) {
            float r = (red[0] + red[1]) + (red[2] + red[3]);
            g_sb[b] = LOGK - logf(r);
            g_tickB[b] = 0;           // reset for graph replay
            __threadfence();
            amFinal = (atomicAdd(&g_tickF, 1u) == BATCH - 1);
        }
        __syncthreads();

        if (amFinal) {
            // one block: fixed-order tree sum over batches -> deterministic
            __shared__ float sm[BATCH];
            sm[t] = g_sb[t];
            __syncthreads();
#pragma unroll
            for (int off = BATCH / 2; off > 0; off >>= 1) {
                if (t < off) sm[t] += sm[t + off];
                __syncthreads();
            }
            if (t == 0) {
                out[0] = sm[0];
                g_tickF = 0;          // reset for graph replay
            }
        }
    }
}

// ---------------------------------------------------------------------------
extern "C" void kernel_launch(void* const* d_in, const int* in_sizes, int n_in,
                              void* d_out, int out_size)
{
    const float* Q0 = (const float*)d_in[0];  // logQ0 [B,K,K]
    const float* Q1 = (const float*)d_in[1];  // logQ1 [B,K,K]
    const float* P0 = (const float*)d_in[2];  // logP0 [B,1,K]
    const float* P1 = (const float*)d_in[3];  // logP1 [B,K,K]
    const float* P2 = (const float*)d_in[4];  // logP2 [B,K,1]

    dim3 g1(2 * NSL, BATCH);
    k_colsum<<<g1, TPB>>>(Q0, Q1, P0);

    dim3 g2(NSL, BATCH);
    k_mid<<<g2, TPB>>>(P1, P2, (float*)d_out);
}

// round 9
// speedup vs baseline: 1.0891x; 1.0891x over previous
#include <cuda_runtime.h>
#include <math.h>

#define BATCH  128
#define KK     512
#define NSL    8      // i-slices of 64 rows
#define SLR    64     // rows per slice
#define TPB    128    // thread owns 4 columns (float4)
#define JSPL   4      // j-chunks in k_final

#define LOGK 6.2383246250395077632f   // log(512)

// Scratch (__device__ globals). Fits in L2 (6 MB << 126 MB); streaming input
// loads use __ldcs (evict-first) so these stay resident.
__device__ float g_Ep0[NSL * BATCH * KK];   // partial col-sums of exp(Q0) (2 MB)
__device__ float g_Ep1[NSL * BATCH * KK];   // partial col-sums of exp(Q1) (2 MB)
__device__ float g_mmp[NSL * BATCH * KK];   // partial mm sums (2 MB)
__device__ float g_sp[BATCH * JSPL];        // per-(b,chunk) t partial sums
__device__ unsigned int g_tickF;            // zero-init; last block resets

__device__ __forceinline__ float4 ldcs4(const float4* p) { return __ldcs(p); }

// ---------------------------------------------------------------------------
// Kernel 1: partial column sums of exp() for Q0 and Q1 (float4, streaming).
// grid = (2*NSL, BATCH) = 2048 blocks, block = 128. No epilogue, no fences.
// ---------------------------------------------------------------------------
__global__ void __launch_bounds__(TPB) k_colsum(const float* __restrict__ Q0,
                                                const float* __restrict__ Q1)
{
    const int which = blockIdx.x >> 3;
    const int slice = blockIdx.x & 7;
    const int b     = blockIdx.y;
    const int t     = threadIdx.x;

    const float* __restrict__ src = which ? Q1 : Q0;
    float* __restrict__ dst = which ? g_Ep1 : g_Ep0;

    const float4* p = (const float4*)(src + (size_t)b * KK * KK
                                          + (size_t)(slice * SLR) * KK) + t;
    const int rs = KK / 4;

    float sx = 0.f, sy = 0.f, sz = 0.f, sw = 0.f;
#pragma unroll
    for (int i = 0; i < SLR; i += 8) {
        float4 a0 = ldcs4(p + (i + 0) * rs);
        float4 a1 = ldcs4(p + (i + 1) * rs);
        float4 a2 = ldcs4(p + (i + 2) * rs);
        float4 a3 = ldcs4(p + (i + 3) * rs);
        float4 a4 = ldcs4(p + (i + 4) * rs);
        float4 a5 = ldcs4(p + (i + 5) * rs);
        float4 a6 = ldcs4(p + (i + 6) * rs);
        float4 a7 = ldcs4(p + (i + 7) * rs);
        sx += __expf(a0.x) + __expf(a1.x) + __expf(a2.x) + __expf(a3.x)
            + __expf(a4.x) + __expf(a5.x) + __expf(a6.x) + __expf(a7.x);
        sy += __expf(a0.y) + __expf(a1.y) + __expf(a2.y) + __expf(a3.y)
            + __expf(a4.y) + __expf(a5.y) + __expf(a6.y) + __expf(a7.y);
        sz += __expf(a0.z) + __expf(a1.z) + __expf(a2.z) + __expf(a3.z)
            + __expf(a4.z) + __expf(a5.z) + __expf(a6.z) + __expf(a7.z);
        sw += __expf(a0.w) + __expf(a1.w) + __expf(a2.w) + __expf(a3.w)
            + __expf(a4.w) + __expf(a5.w) + __expf(a6.w) + __expf(a7.w);
    }
    ((float4*)(dst + ((size_t)slice * BATCH + b) * KK))[t] =
        make_float4(sx, sy, sz, sw);
}

// ---------------------------------------------------------------------------
// Kernel 2: partial mm[b,j] = sum_{i in slice} ew[b,i]*exp(P1[b,i,j]).
// ew computed inline in a slice-local prologue (L2-hit partials + P0 + div).
// grid = (NSL, BATCH) = 1024 blocks, block = 128.
// ---------------------------------------------------------------------------
__global__ void __launch_bounds__(TPB) k_mid(const float* __restrict__ P0,
                                             const float* __restrict__ P1)
{
    const int slice = blockIdx.x;
    const int b     = blockIdx.y;
    const int t     = threadIdx.x;
    const int i0    = slice * SLR;

    __shared__ float ew[SLR];
    if (t < SLR) {
        const int i = i0 + t;
        float e1 = g_Ep1[((size_t)0 * BATCH + b) * KK + i];
#pragma unroll
        for (int s = 1; s < NSL; s++)
            e1 += g_Ep1[((size_t)s * BATCH + b) * KK + i];
        ew[t] = __expf(P0[b * KK + i]) * (float)KK / e1;
    }
    __syncthreads();

    const float4* p = (const float4*)(P1 + (size_t)b * KK * KK
                                         + (size_t)i0 * KK) + t;
    const int rs = KK / 4;

    float sx = 0.f, sy = 0.f, sz = 0.f, sw = 0.f;
#pragma unroll
    for (int i = 0; i < SLR; i += 8) {
        float4 a0 = ldcs4(p + (i + 0) * rs);
        float4 a1 = ldcs4(p + (i + 1) * rs);
        float4 a2 = ldcs4(p + (i + 2) * rs);
        float4 a3 = ldcs4(p + (i + 3) * rs);
        float4 a4 = ldcs4(p + (i + 4) * rs);
        float4 a5 = ldcs4(p + (i + 5) * rs);
        float4 a6 = ldcs4(p + (i + 6) * rs);
        float4 a7 = ldcs4(p + (i + 7) * rs);
        float w0 = ew[i + 0], w1 = ew[i + 1], w2 = ew[i + 2], w3 = ew[i + 3];
        float w4 = ew[i + 4], w5 = ew[i + 5], w6 = ew[i + 6], w7 = ew[i + 7];
        sx += w0 * __expf(a0.x) + w1 * __expf(a1.x)
            + w2 * __expf(a2.x) + w3 * __expf(a3.x)
            + w4 * __expf(a4.x) + w5 * __expf(a5.x)
            + w6 * __expf(a6.x) + w7 * __expf(a7.x);
        sy += w0 * __expf(a0.y) + w1 * __expf(a1.y)
            + w2 * __expf(a2.y) + w3 * __expf(a3.y)
            + w4 * __expf(a4.y) + w5 * __expf(a5.y)
            + w6 * __expf(a6.y) + w7 * __expf(a7.y);
        sz += w0 * __expf(a0.z) + w1 * __expf(a1.z)
            + w2 * __expf(a2.z) + w3 * __expf(a3.z)
            + w4 * __expf(a4.z) + w5 * __expf(a5.z)
            + w6 * __expf(a6.z) + w7 * __expf(a7.z);
        sw += w0 * __expf(a0.w) + w1 * __expf(a1.w)
            + w2 * __expf(a2.w) + w3 * __expf(a3.w)
            + w4 * __expf(a4.w) + w5 * __expf(a5.w)
            + w6 * __expf(a6.w) + w7 * __expf(a7.w);
    }
    ((float4*)(g_mmp + ((size_t)slice * BATCH + b) * KK))[t] =
        make_float4(sx, sy, sz, sw);
}

// ---------------------------------------------------------------------------
// Kernel 3: t partials + deterministic finish.
// grid = (JSPL, BATCH) = 512 blocks, block = 128. Thread owns one j: reduces
// NSL mmp partials AND NSL E0 partials (17 independent loads in flight),
// applies exp(P2)/E0, block-reduces -> g_sp. Last-finishing block (ticket)
// does the fixed-order per-batch log + batch tree-sum into out.
// ---------------------------------------------------------------------------
__global__ void __launch_bounds__(TPB) k_final(const float* __restrict__ P2,
                                               float* __restrict__ out)
{
    const int js = blockIdx.x;
    const int b  = blockIdx.y;
    const int t  = threadIdx.x;
    const int j  = js * TPB + t;

    float m = 0.f, e0 = 0.f;
#pragma unroll
    for (int s = 0; s < NSL; s++) {
        m  += g_mmp[((size_t)s * BATCH + b) * KK + j];
        e0 += g_Ep0[((size_t)s * BATCH + b) * KK + j];
    }
    float acc = m / e0 * __expf(P2[b * KK + j]);

#pragma unroll
    for (int o = 16; o; o >>= 1)
        acc += __shfl_down_sync(0xFFFFFFFFu, acc, o);

    __shared__ float red[4];
    if ((t & 31) == 0) red[t >> 5] = acc;
    __syncthreads();

    __shared__ bool amLast;
    if (t == 0) {
        g_sp[b * JSPL + js] = (red[0] + red[1]) + (red[2] + red[3]);
        __threadfence();
        amLast = (atomicAdd(&g_tickF, 1u) == BATCH * JSPL - 1);
    }
    __syncthreads();

    if (amLast) {
        __shared__ float sm[BATCH];
        float s = (g_sp[t * JSPL + 0] + g_sp[t * JSPL + 1])
                + (g_sp[t * JSPL + 2] + g_sp[t * JSPL + 3]);
        sm[t] = LOGK - logf(s);
        __syncthreads();
#pragma unroll
        for (int off = BATCH / 2; off > 0; off >>= 1) {
            if (t < off) sm[t] += sm[t + off];
            __syncthreads();
        }
        if (t == 0) {
            out[0] = sm[0];
            g_tickF = 0;   // reset for graph replay
        }
    }
}

// ---------------------------------------------------------------------------
extern "C" void kernel_launch(void* const* d_in, const int* in_sizes, int n_in,
                              void* d_out, int out_size)
{
    const float* Q0 = (const float*)d_in[0];  // logQ0 [B,K,K]
    const float* Q1 = (const float*)d_in[1];  // logQ1 [B,K,K]
    const float* P0 = (const float*)d_in[2];  // logP0 [B,1,K]
    const float* P1 = (const float*)d_in[3];  // logP1 [B,K,K]
    const float* P2 = (const float*)d_in[4];  // logP2 [B,K,1]

    dim3 g1(2 * NSL, BATCH);
    k_colsum<<<g1, TPB>>>(Q0, Q1);

    dim3 g2(NSL, BATCH);
    k_mid<<<g2, TPB>>>(P0, P1);

    dim3 g3(JSPL, BATCH);
    k_final<<<g3, TPB>>>(P2, (float*)d_out);
}

// round 10
// speedup vs baseline: 1.1209x; 1.0292x over previous
#include <cuda_runtime.h>
#include <math.h>

#define BATCH  128
#define KK     512
#define NSL    8      // i-slices of 64 rows
#define SLR    64     // rows per slice
#define TPB    128    // thread owns 4 columns (float4)
#define JSPL   4      // j-chunks in k_final

#define LOGK 6.2383246250395077632f   // log(512)

// Scratch (__device__ globals). Fits in L2 (6 MB << 126 MB); streaming input
// loads use __ldcs (evict-first) so these stay resident.
__device__ float g_Ep0[NSL * BATCH * KK];   // partial col-sums of exp(Q0) (2 MB)
__device__ float g_Ep1[NSL * BATCH * KK];   // partial col-sums of exp(Q1) (2 MB)
__device__ float g_mmp[NSL * BATCH * KK];   // partial mm sums (2 MB)
__device__ float g_sp[BATCH * JSPL];        // per-(b,chunk) t partial sums
__device__ unsigned int g_tickF;            // zero-init; last block resets

__device__ __forceinline__ float4 ldcs4(const float4* p) { return __ldcs(p); }

// ---------------------------------------------------------------------------
// Kernel 1: partial column sums of exp() for Q0 and Q1 (float4, streaming).
// grid = (2*NSL, BATCH) = 2048 blocks, block = 128.
// __launch_bounds__(128, 14): cap regs at 36 so all 2048 blocks fit in ONE
// wave (148 SM x 14 blocks = 2072). Load batch = 4 float4 (64 B in flight
// per thread; ~114 KB/SM, far above the latency-hiding requirement).
// ---------------------------------------------------------------------------
__global__ void __launch_bounds__(TPB, 14) k_colsum(const float* __restrict__ Q0,
                                                    const float* __restrict__ Q1)
{
    const int which = blockIdx.x >> 3;
    const int slice = blockIdx.x & 7;
    const int b     = blockIdx.y;
    const int t     = threadIdx.x;

    const float* __restrict__ src = which ? Q1 : Q0;
    float* __restrict__ dst = which ? g_Ep1 : g_Ep0;

    const float4* p = (const float4*)(src + (size_t)b * KK * KK
                                          + (size_t)(slice * SLR) * KK) + t;
    const int rs = KK / 4;

    float sx = 0.f, sy = 0.f, sz = 0.f, sw = 0.f;
#pragma unroll
    for (int i = 0; i < SLR; i += 4) {
        float4 a0 = ldcs4(p + (i + 0) * rs);
        float4 a1 = ldcs4(p + (i + 1) * rs);
        float4 a2 = ldcs4(p + (i + 2) * rs);
        float4 a3 = ldcs4(p + (i + 3) * rs);
        sx += __expf(a0.x) + __expf(a1.x) + __expf(a2.x) + __expf(a3.x);
        sy += __expf(a0.y) + __expf(a1.y) + __expf(a2.y) + __expf(a3.y);
        sz += __expf(a0.z) + __expf(a1.z) + __expf(a2.z) + __expf(a3.z);
        sw += __expf(a0.w) + __expf(a1.w) + __expf(a2.w) + __expf(a3.w);
    }
    ((float4*)(dst + ((size_t)slice * BATCH + b) * KK))[t] =
        make_float4(sx, sy, sz, sw);
}

// ---------------------------------------------------------------------------
// Kernel 2: partial mm[b,j] = sum_{i in slice} ew[b,i]*exp(P1[b,i,j]).
// ew computed inline in a slice-local prologue (L2-hit partials + P0 + div).
// grid = (NSL, BATCH) = 1024 blocks, block = 128. Single wave already.
// ---------------------------------------------------------------------------
__global__ void __launch_bounds__(TPB) k_mid(const float* __restrict__ P0,
                                             const float* __restrict__ P1)
{
    const int slice = blockIdx.x;
    const int b     = blockIdx.y;
    const int t     = threadIdx.x;
    const int i0    = slice * SLR;

    __shared__ float ew[SLR];
    if (t < SLR) {
        const int i = i0 + t;
        float e1 = g_Ep1[((size_t)0 * BATCH + b) * KK + i];
#pragma unroll
        for (int s = 1; s < NSL; s++)
            e1 += g_Ep1[((size_t)s * BATCH + b) * KK + i];
        ew[t] = __expf(P0[b * KK + i]) * (float)KK / e1;
    }
    __syncthreads();

    const float4* p = (const float4*)(P1 + (size_t)b * KK * KK
                                         + (size_t)i0 * KK) + t;
    const int rs = KK / 4;

    float sx = 0.f, sy = 0.f, sz = 0.f, sw = 0.f;
#pragma unroll
    for (int i = 0; i < SLR; i += 8) {
        float4 a0 = ldcs4(p + (i + 0) * rs);
        float4 a1 = ldcs4(p + (i + 1) * rs);
        float4 a2 = ldcs4(p + (i + 2) * rs);
        float4 a3 = ldcs4(p + (i + 3) * rs);
        float4 a4 = ldcs4(p + (i + 4) * rs);
        float4 a5 = ldcs4(p + (i + 5) * rs);
        float4 a6 = ldcs4(p + (i + 6) * rs);
        float4 a7 = ldcs4(p + (i + 7) * rs);
        float w0 = ew[i + 0], w1 = ew[i + 1], w2 = ew[i + 2], w3 = ew[i + 3];
        float w4 = ew[i + 4], w5 = ew[i + 5], w6 = ew[i + 6], w7 = ew[i + 7];
        sx += w0 * __expf(a0.x) + w1 * __expf(a1.x)
            + w2 * __expf(a2.x) + w3 * __expf(a3.x)
            + w4 * __expf(a4.x) + w5 * __expf(a5.x)
            + w6 * __expf(a6.x) + w7 * __expf(a7.x);
        sy += w0 * __expf(a0.y) + w1 * __expf(a1.y)
            + w2 * __expf(a2.y) + w3 * __expf(a3.y)
            + w4 * __expf(a4.y) + w5 * __expf(a5.y)
            + w6 * __expf(a6.y) + w7 * __expf(a7.y);
        sz += w0 * __expf(a0.z) + w1 * __expf(a1.z)
            + w2 * __expf(a2.z) + w3 * __expf(a3.z)
            + w4 * __expf(a4.z) + w5 * __expf(a5.z)
            + w6 * __expf(a6.z) + w7 * __expf(a7.z);
        sw += w0 * __expf(a0.w) + w1 * __expf(a1.w)
            + w2 * __expf(a2.w) + w3 * __expf(a3.w)
            + w4 * __expf(a4.w) + w5 * __expf(a5.w)
            + w6 * __expf(a6.w) + w7 * __expf(a7.w);
    }
    ((float4*)(g_mmp + ((size_t)slice * BATCH + b) * KK))[t] =
        make_float4(sx, sy, sz, sw);
}

// ---------------------------------------------------------------------------
// Kernel 3: t partials + deterministic finish.
// grid = (JSPL, BATCH) = 512 blocks, block = 128. Thread owns one j: reduces
// NSL mmp partials AND NSL E0 partials (17 independent loads in flight),
// applies exp(P2)/E0, block-reduces -> g_sp. Last-finishing block (ticket)
// does the fixed-order per-batch log + batch tree-sum into out.
// ---------------------------------------------------------------------------
__global__ void __launch_bounds__(TPB) k_final(const float* __restrict__ P2,
                                               float* __restrict__ out)
{
    const int js = blockIdx.x;
    const int b  = blockIdx.y;
    const int t  = threadIdx.x;
    const int j  = js * TPB + t;

    float m = 0.f, e0 = 0.f;
#pragma unroll
    for (int s = 0; s < NSL; s++) {
        m  += g_mmp[((size_t)s * BATCH + b) * KK + j];
        e0 += g_Ep0[((size_t)s * BATCH + b) * KK + j];
    }
    float acc = m / e0 * __expf(P2[b * KK + j]);

#pragma unroll
    for (int o = 16; o; o >>= 1)
        acc += __shfl_down_sync(0xFFFFFFFFu, acc, o);

    __shared__ float red[4];
    if ((t & 31) == 0) red[t >> 5] = acc;
    __syncthreads();

    __shared__ bool amLast;
    if (t == 0) {
        g_sp[b * JSPL + js] = (red[0] + red[1]) + (red[2] + red[3]);
        __threadfence();
        amLast = (atomicAdd(&g_tickF, 1u) == BATCH * JSPL - 1);
    }
    __syncthreads();

    if (amLast) {
        __shared__ float sm[BATCH];
        float s = (g_sp[t * JSPL + 0] + g_sp[t * JSPL + 1])
                + (g_sp[t * JSPL + 2] + g_sp[t * JSPL + 3]);
        sm[t] = LOGK - logf(s);
        __syncthreads();
#pragma unroll
        for (int off = BATCH / 2; off > 0; off >>= 1) {
            if (t < off) sm[t] += sm[t + off];
            __syncthreads();
        }
        if (t == 0) {
            out[0] = sm[0];
            g_tickF = 0;   // reset for graph replay
        }
    }
}

// ---------------------------------------------------------------------------
extern "C" void kernel_launch(void* const* d_in, const int* in_sizes, int n_in,
                              void* d_out, int out_size)
{
    const float* Q0 = (const float*)d_in[0];  // logQ0 [B,K,K]
    const float* Q1 = (const float*)d_in[1];  // logQ1 [B,K,K]
    const float* P0 = (const float*)d_in[2];  // logP0 [B,1,K]
    const float* P1 = (const float*)d_in[3];  // logP1 [B,K,K]
    const float* P2 = (const float*)d_in[4];  // logP2 [B,K,1]

    dim3 g1(2 * NSL, BATCH);
    k_colsum<<<g1, TPB>>>(Q0, Q1);

    dim3 g2(NSL, BATCH);
    k_mid<<<g2, TPB>>>(P0, P1);

    dim3 g3(JSPL, BATCH);
    k_final<<<g3, TPB>>>(P2, (float*)d_out);
}

// round 11
// speedup vs baseline: 1.1255x; 1.0041x over previous
#include <cuda_runtime.h>
#include <math.h>

#define BATCH  128
#define KK     512
#define NSL    8      // i-slices of 64 rows
#define SLR    64     // rows per slice
#define TPB    128    // thread owns 4 columns (float4)
#define JSPL   4      // j-chunks in k_final

#define LOGK 6.2383246250395077632f   // log(512)

// Scratch (__device__ globals). Fits in L2 (6 MB << 126 MB); streaming input
// loads use __ldcs (evict-first) so these stay resident.
__device__ float g_Ep0[NSL * BATCH * KK];   // partial col-sums of exp(Q0) (2 MB)
__device__ float g_Ep1[NSL * BATCH * KK];   // partial col-sums of exp(Q1) (2 MB)
__device__ float g_mmp[NSL * BATCH * KK];   // partial mm sums (2 MB)
__device__ float g_sp[BATCH * JSPL];        // per-(b,chunk) t partial sums
__device__ unsigned int g_tickF;            // zero-init; last block resets

__device__ __forceinline__ float4 ldcs4(const float4* p) { return __ldcs(p); }

// ---------------------------------------------------------------------------
// Kernel 1: partial column sums of exp(Q1) only (E1 partials for ew).
// grid = (NSL, BATCH) = 1024 blocks, block = 128.
// ---------------------------------------------------------------------------
__global__ void __launch_bounds__(TPB, 14) k_colsum_q1(const float* __restrict__ Q1)
{
    const int slice = blockIdx.x;
    const int b     = blockIdx.y;
    const int t     = threadIdx.x;

    const float4* p = (const float4*)(Q1 + (size_t)b * KK * KK
                                         + (size_t)(slice * SLR) * KK) + t;
    const int rs = KK / 4;

    float sx = 0.f, sy = 0.f, sz = 0.f, sw = 0.f;
#pragma unroll
    for (int i = 0; i < SLR; i += 4) {
        float4 a0 = ldcs4(p + (i + 0) * rs);
        float4 a1 = ldcs4(p + (i + 1) * rs);
        float4 a2 = ldcs4(p + (i + 2) * rs);
        float4 a3 = ldcs4(p + (i + 3) * rs);
        sx += __expf(a0.x) + __expf(a1.x) + __expf(a2.x) + __expf(a3.x);
        sy += __expf(a0.y) + __expf(a1.y) + __expf(a2.y) + __expf(a3.y);
        sz += __expf(a0.z) + __expf(a1.z) + __expf(a2.z) + __expf(a3.z);
        sw += __expf(a0.w) + __expf(a1.w) + __expf(a2.w) + __expf(a3.w);
    }
    ((float4*)(g_Ep1 + ((size_t)slice * BATCH + b) * KK))[t] =
        make_float4(sx, sy, sz, sw);
}

// ---------------------------------------------------------------------------
// Kernel 2 (heterogeneous, one wave): grid = (2*NSL, BATCH) = 2048 blocks.
//   blockIdx.x <  NSL : mid-path  — mmp[b,j] partial over P1 slice, using
//                       ew built inline from L2-hot g_Ep1 + P0.
//   blockIdx.x >= NSL : colsum-path over the matching Q0 slice.
// Flavors interleave across SMs via the modular block-ID placement, so both
// stream concurrently; Q0 work fills the mid-path's ramp and tail.
// __launch_bounds__(128, 14) keeps regs <= 36 -> 2048 <= 148*14 = one wave.
// ---------------------------------------------------------------------------
__global__ void __launch_bounds__(TPB, 14) k_mid_q0(const float* __restrict__ P0,
                                                    const float* __restrict__ P1,
                                                    const float* __restrict__ Q0)
{
    const int b = blockIdx.y;
    const int t = threadIdx.x;
    const int rs = KK / 4;

    if (blockIdx.x < NSL) {
        // ----- mid path: P1 slice -----
        const int slice = blockIdx.x;
        const int i0    = slice * SLR;

        __shared__ float ew[SLR];
        if (t < SLR) {
            const int i = i0 + t;
            float e1 = g_Ep1[((size_t)0 * BATCH + b) * KK + i];
#pragma unroll
            for (int s = 1; s < NSL; s++)
                e1 += g_Ep1[((size_t)s * BATCH + b) * KK + i];
            ew[t] = __expf(P0[b * KK + i]) * (float)KK / e1;
        }
        __syncthreads();

        const float4* p = (const float4*)(P1 + (size_t)b * KK * KK
                                             + (size_t)i0 * KK) + t;

        float sx = 0.f, sy = 0.f, sz = 0.f, sw = 0.f;
#pragma unroll
        for (int i = 0; i < SLR; i += 4) {
            float4 a0 = ldcs4(p + (i + 0) * rs);
            float4 a1 = ldcs4(p + (i + 1) * rs);
            float4 a2 = ldcs4(p + (i + 2) * rs);
            float4 a3 = ldcs4(p + (i + 3) * rs);
            float w0 = ew[i + 0], w1 = ew[i + 1], w2 = ew[i + 2], w3 = ew[i + 3];
            sx += w0 * __expf(a0.x) + w1 * __expf(a1.x)
                + w2 * __expf(a2.x) + w3 * __expf(a3.x);
            sy += w0 * __expf(a0.y) + w1 * __expf(a1.y)
                + w2 * __expf(a2.y) + w3 * __expf(a3.y);
            sz += w0 * __expf(a0.z) + w1 * __expf(a1.z)
                + w2 * __expf(a2.z) + w3 * __expf(a3.z);
            sw += w0 * __expf(a0.w) + w1 * __expf(a1.w)
                + w2 * __expf(a2.w) + w3 * __expf(a3.w);
        }
        ((float4*)(g_mmp + ((size_t)slice * BATCH + b) * KK))[t] =
            make_float4(sx, sy, sz, sw);
    } else {
        // ----- colsum path: Q0 slice -----
        const int slice = blockIdx.x - NSL;

        const float4* p = (const float4*)(Q0 + (size_t)b * KK * KK
                                             + (size_t)(slice * SLR) * KK) + t;

        float sx = 0.f, sy = 0.f, sz = 0.f, sw = 0.f;
#pragma unroll
        for (int i = 0; i < SLR; i += 4) {
            float4 a0 = ldcs4(p + (i + 0) * rs);
            float4 a1 = ldcs4(p + (i + 1) * rs);
            float4 a2 = ldcs4(p + (i + 2) * rs);
            float4 a3 = ldcs4(p + (i + 3) * rs);
            sx += __expf(a0.x) + __expf(a1.x) + __expf(a2.x) + __expf(a3.x);
            sy += __expf(a0.y) + __expf(a1.y) + __expf(a2.y) + __expf(a3.y);
            sz += __expf(a0.z) + __expf(a1.z) + __expf(a2.z) + __expf(a3.z);
            sw += __expf(a0.w) + __expf(a1.w) + __expf(a2.w) + __expf(a3.w);
        }
        ((float4*)(g_Ep0 + ((size_t)slice * BATCH + b) * KK))[t] =
            make_float4(sx, sy, sz, sw);
    }
}

// ---------------------------------------------------------------------------
// Kernel 3: t partials + deterministic finish.
// grid = (JSPL, BATCH) = 512 blocks, block = 128. Thread owns one j: reduces
// NSL mmp partials AND NSL E0 partials, applies exp(P2)/E0, block-reduces.
// Last-finishing block (ticket) does the fixed-order per-batch log + batch
// tree-sum into out, then resets the ticket for graph replay.
// ---------------------------------------------------------------------------
__global__ void __launch_bounds__(TPB) k_final(const float* __restrict__ P2,
                                               float* __restrict__ out)
{
    const int js = blockIdx.x;
    const int b  = blockIdx.y;
    const int t  = threadIdx.x;
    const int j  = js * TPB + t;

    float m = 0.f, e0 = 0.f;
#pragma unroll
    for (int s = 0; s < NSL; s++) {
        m  += g_mmp[((size_t)s * BATCH + b) * KK + j];
        e0 += g_Ep0[((size_t)s * BATCH + b) * KK + j];
    }
    float acc = m / e0 * __expf(P2[b * KK + j]);

#pragma unroll
    for (int o = 16; o; o >>= 1)
        acc += __shfl_down_sync(0xFFFFFFFFu, acc, o);

    __shared__ float red[4];
    if ((t & 31) == 0) red[t >> 5] = acc;
    __syncthreads();

    __shared__ bool amLast;
    if (t == 0) {
        g_sp[b * JSPL + js] = (red[0] + red[1]) + (red[2] + red[3]);
        __threadfence();
        amLast = (atomicAdd(&g_tickF, 1u) == BATCH * JSPL - 1);
    }
    __syncthreads();

    if (amLast) {
        __shared__ float sm[BATCH];
        float s = (g_sp[t * JSPL + 0] + g_sp[t * JSPL + 1])
                + (g_sp[t * JSPL + 2] + g_sp[t * JSPL + 3]);
        sm[t] = LOGK - logf(s);
        __syncthreads();
#pragma unroll
        for (int off = BATCH / 2; off > 0; off >>= 1) {
            if (t < off) sm[t] += sm[t + off];
            __syncthreads();
        }
        if (t == 0) {
            out[0] = sm[0];
            g_tickF = 0;   // reset for graph replay
        }
    }
}

// ---------------------------------------------------------------------------
extern "C" void kernel_launch(void* const* d_in, const int* in_sizes, int n_in,
                              void* d_out, int out_size)
{
    const float* Q0 = (const float*)d_in[0];  // logQ0 [B,K,K]
    const float* Q1 = (const float*)d_in[1];  // logQ1 [B,K,K]
    const float* P0 = (const float*)d_in[2];  // logP0 [B,1,K]
    const float* P1 = (const float*)d_in[3];  // logP1 [B,K,K]
    const float* P2 = (const float*)d_in[4];  // logP2 [B,K,1]

    dim3 g1(NSL, BATCH);
    k_colsum_q1<<<g1, TPB>>>(Q1);

    dim3 g2(2 * NSL, BATCH);
    k_mid_q0<<<g2, TPB>>>(P0, P1, Q0);

    dim3 g3(JSPL, BATCH);
    k_final<<<g3, TPB>>>(P2, (float*)d_out);
}